// round 12
// baseline (speedup 1.0000x reference)
#include <cuda_runtime.h>
#include <cuda_fp16.h>
#include <mma.h>
#include <cstdint>

using namespace nvcuda;

#define TOK    262144          // 4*256*256 tokens
#define CDIM   192

// ---------------- scratch (device globals; no allocation) ----------------
__device__ __half g_ln  [(size_t)TOK * 192];   // LN1 (window layout) then LN2 (token layout)
__device__ __half g_big [(size_t)TOK * 768];   // qkv (576 wide) then fc1 activation (768 wide)
__device__ __half g_ow  [(size_t)TOK * 192];   // attention output, window layout
__device__ __half g_xo  [(size_t)TOK * 192];   // post-attention residual, token layout (fp16)
__device__ __half g_wqkv_h[192 * 576];
__device__ __half g_wproj_h[192 * 192];
__device__ __half g_wfc1_h[192 * 768];
__device__ __half g_wfc2_h[768 * 192];

// ---------------- cp.async helpers ----------------
__device__ __forceinline__ void cp_async16(void* smem_dst, const void* gmem_src) {
    uint32_t s = (uint32_t)__cvta_generic_to_shared(smem_dst);
    asm volatile("cp.async.cg.shared.global [%0], [%1], 16;\n" :: "r"(s), "l"(gmem_src));
}
__device__ __forceinline__ void cp_commit() {
    asm volatile("cp.async.commit_group;\n" ::: "memory");
}
template<int N>
__device__ __forceinline__ void cp_wait() {
    asm volatile("cp.async.wait_group %0;\n" :: "n"(N) : "memory");
}

// ---------------- fused fp32 -> fp16 conversion of all four weights ----------------
__global__ __launch_bounds__(256) void f2h_all_kernel(const float* __restrict__ w0, __half* o0, int n0,
                                                      const float* __restrict__ w1, __half* o1, int n1,
                                                      const float* __restrict__ w2, __half* o2, int n2,
                                                      const float* __restrict__ w3, __half* o3, int n3)
{
    int i = blockIdx.x * 256 + threadIdx.x;
    const float* src; __half* dst;
    if (i < n0)                    { src = w0; dst = o0; }
    else if ((i -= n0) < n1)       { src = w1; dst = o1; }
    else if ((i -= n1) < n2)       { src = w2; dst = o2; }
    else if ((i -= n2) < n3)       { src = w3; dst = o3; }
    else return;
    float4 v = *(const float4*)(src + (size_t)i * 4);
    __half2 h0 = __floats2half2_rn(v.x, v.y);
    __half2 h1 = __floats2half2_rn(v.z, v.w);
    *(uint2*)(dst + (size_t)i * 4) = make_uint2(*(uint32_t*)&h0, *(uint32_t*)&h1);
}

// ---------------- LayerNorm (one warp per token), templated input, fp16 output ----------------
template<bool WINDOW_DST, typename T>
__global__ __launch_bounds__(256) void ln_kernel(const T* __restrict__ x,
                                                 const float* __restrict__ g,
                                                 const float* __restrict__ b,
                                                 __half* __restrict__ out)
{
    int tok  = blockIdx.x * (blockDim.x >> 5) + (threadIdx.x >> 5);
    int lane = threadIdx.x & 31;
    const T* row = x + (size_t)tok * CDIM;
    float v[6];
    float s = 0.f, s2 = 0.f;
#pragma unroll
    for (int k = 0; k < 6; k++) {
        v[k] = (float)row[lane + 32 * k];
        s  += v[k];
        s2 += v[k] * v[k];
    }
#pragma unroll
    for (int o = 16; o > 0; o >>= 1) {
        s  += __shfl_xor_sync(0xffffffffu, s,  o);
        s2 += __shfl_xor_sync(0xffffffffu, s2, o);
    }
    float mean = s * (1.f / 192.f);
    float var  = s2 * (1.f / 192.f) - mean * mean;
    float inv  = rsqrtf(var + 1e-5f);

    size_t drow;
    if (WINDOW_DST) {
        int bb  = tok >> 16;
        int rem = tok & 65535;
        int h   = rem >> 8;
        int w   = rem & 255;
        int win = (bb << 10) + ((h >> 3) << 5) + (w >> 3);
        int n   = ((h & 7) << 3) + (w & 7);
        drow = (size_t)win * 64 + n;
    } else {
        drow = (size_t)tok;
    }
    __half* orow = out + drow * CDIM;
#pragma unroll
    for (int k = 0; k < 6; k++) {
        int c = lane + 32 * k;
        orow[c] = __float2half_rn((v[k] - mean) * inv * g[c] + b[c]);
    }
}

// ---------------- GEMM: fp16 wmma, 128x96 tile, 128 thr (64x48 warp tile), 3-stage ----------------
#define GBM 128
#define GBN 96
#define GBK 64
#define NTHRG 128

#define ALDH 72                   // 64 + 8 halves pad
#define BLDH 104                  // 96 + 8 halves pad
#define SA_HALF (GBM * ALDH)      // 9216 halves
#define SB_HALF (GBK * BLDH)      // 6656 halves
#define STAGE_HALF (SA_HALF + SB_HALF)
#define GEMM_DYN (3 * STAGE_HALF * 2)   // 95232 B; epilogue csm 128*100*4 = 51200 fits
#define CLD 100

enum { EPI_QKV = 0, EPI_PROJ = 1, EPI_FC1 = 2, EPI_FC2 = 3 };

// A: [M][KDIM] half row-major; B: [KDIM][NDIM] half row-major.
// EPI_PROJ: res = x (fp32), out = xo (fp16, token scatter).
// EPI_FC2:  res = xo (fp16), out = final (fp32).
template<int KDIM, int NDIM, int EPI>
__global__ __launch_bounds__(NTHRG, 2) void gemm_kernel(const __half* __restrict__ A,
                                                        const __half* __restrict__ B,
                                                        const float* __restrict__ bias,
                                                        const void* __restrict__ res_v,
                                                        void* __restrict__ out_v)
{
    extern __shared__ char dynsm[];
    __half* sbase = (__half*)dynsm;
    float*  csm   = (float*)dynsm;

    const int bn   = blockIdx.x;
    const int bm   = blockIdx.y;
    const int tid  = threadIdx.x;
    const int warp = tid >> 5;
    const int wr   = warp >> 1;   // 0..1 : 64-row group
    const int wc   = warp & 1;    // 0..1 : 48-col group

    const __half* Abase = A + (size_t)(bm * GBM) * KDIM;
    const __half* Bbase = B + (size_t)bn * GBN;

    wmma::fragment<wmma::accumulator, 16, 16, 16, float> acc[4][3];
#pragma unroll
    for (int i = 0; i < 4; i++)
#pragma unroll
        for (int j = 0; j < 3; j++) wmma::fill_fragment(acc[i][j], 0.f);

    auto issue_stage = [&](int st, int k0) {
        __half* sa = sbase + st * STAGE_HALF;
        __half* sb = sa + SA_HALF;
        // A tile 128x64 halves: 1024 x 16B lines, 8/thread
#pragma unroll
        for (int s = 0; s < 8; s++) {
            int line = tid + s * NTHRG;
            int r = line >> 3, c8 = line & 7;
            cp_async16(&sa[r * ALDH + c8 * 8],
                       Abase + (size_t)r * KDIM + k0 + c8 * 8);
        }
        // B tile 64x96 halves: 768 x 16B lines, 6/thread
#pragma unroll
        for (int s = 0; s < 6; s++) {
            int line = tid + s * NTHRG;
            int r = line / 12, c8 = line % 12;
            cp_async16(&sb[r * BLDH + c8 * 8],
                       Bbase + (size_t)(k0 + r) * NDIM + c8 * 8);
        }
        cp_commit();
    };

    constexpr int NK = KDIM / GBK;
    issue_stage(0, 0);
    if (NK > 1) issue_stage(1, GBK);

    // Single-barrier mainloop: wait(cur) -> barrier -> issue(kt+2) -> compute(kt).
#pragma unroll 1
    for (int kt = 0; kt < NK; kt++) {
        if (kt + 1 < NK) cp_wait<1>(); else cp_wait<0>();
        __syncthreads();
        if (kt + 2 < NK) issue_stage((kt + 2) % 3, (kt + 2) * GBK);

        const __half* sa = sbase + (kt % 3) * STAGE_HALF;
        const __half* sb = sa + SA_HALF;
#pragma unroll
        for (int kk = 0; kk < GBK; kk += 16) {
            wmma::fragment<wmma::matrix_a, 16, 16, 16, __half, wmma::row_major> af[4];
            wmma::fragment<wmma::matrix_b, 16, 16, 16, __half, wmma::row_major> bf[3];
#pragma unroll
            for (int i = 0; i < 4; i++)
                wmma::load_matrix_sync(af[i], &sa[(wr * 64 + i * 16) * ALDH + kk], ALDH);
#pragma unroll
            for (int j = 0; j < 3; j++)
                wmma::load_matrix_sync(bf[j], &sb[kk * BLDH + wc * 48 + j * 16], BLDH);
#pragma unroll
            for (int i = 0; i < 4; i++)
#pragma unroll
                for (int j = 0; j < 3; j++)
                    wmma::mma_sync(acc[i][j], af[i], bf[j], acc[i][j]);
        }
    }
    __syncthreads();   // all compute done before csm overwrites stage buffers

#pragma unroll
    for (int i = 0; i < 4; i++)
#pragma unroll
        for (int j = 0; j < 3; j++)
            wmma::store_matrix_sync(&csm[(wr * 64 + i * 16) * CLD + wc * 48 + j * 16],
                                    acc[i][j], CLD, wmma::mem_row_major);
    __syncthreads();

    // epilogue: 128x96 = 3072 float4-groups, 24 per thread
#pragma unroll
    for (int e = tid; e < GBM * (GBN / 4); e += NTHRG) {
        int r  = e / 24;
        int c4 = e % 24;
        int gcol = bn * GBN + c4 * 4;
        size_t grow = (size_t)bm * GBM + r;
        float4 v  = *(float4*)&csm[r * CLD + c4 * 4];
        float4 bb = *(const float4*)&bias[gcol];
        v.x += bb.x; v.y += bb.y; v.z += bb.z; v.w += bb.w;

        if constexpr (EPI == EPI_QKV) {
            __half* out = (__half*)out_v;
            __half2 h0 = __floats2half2_rn(v.x, v.y);
            __half2 h1 = __floats2half2_rn(v.z, v.w);
            *(uint2*)&out[grow * NDIM + gcol] = make_uint2(*(uint32_t*)&h0, *(uint32_t*)&h1);
        } else if constexpr (EPI == EPI_PROJ) {
            __half* out = (__half*)out_v;              // xo fp16
            const float* res = (const float*)res_v;    // original x fp32
            int rg  = (int)grow;
            int win = rg >> 6, n = rg & 63;
            int bbi = win >> 10, wrw = win & 1023;
            int h   = ((wrw >> 5) << 3) + (n >> 3);
            int w   = ((wrw & 31) << 3) + (n & 7);
            size_t t = ((size_t)bbi << 16) + ((size_t)h << 8) + (size_t)w;
            float4 rr = *(const float4*)&res[t * CDIM + gcol];
            v.x += rr.x; v.y += rr.y; v.z += rr.z; v.w += rr.w;
            __half2 h0 = __floats2half2_rn(v.x, v.y);
            __half2 h1 = __floats2half2_rn(v.z, v.w);
            *(uint2*)&out[t * CDIM + gcol] = make_uint2(*(uint32_t*)&h0, *(uint32_t*)&h1);
        } else if constexpr (EPI == EPI_FC1) {
            __half* out = (__half*)out_v;
            v.x *= normcdff(v.x); v.y *= normcdff(v.y);
            v.z *= normcdff(v.z); v.w *= normcdff(v.w);
            __half2 h0 = __floats2half2_rn(v.x, v.y);
            __half2 h1 = __floats2half2_rn(v.z, v.w);
            *(uint2*)&out[grow * NDIM + gcol] = make_uint2(*(uint32_t*)&h0, *(uint32_t*)&h1);
        } else {  // EPI_FC2
            float* out = (float*)out_v;
            const __half* res = (const __half*)res_v;  // xo fp16
            uint2 raw = *(const uint2*)&res[grow * (size_t)CDIM + gcol];
            float2 r0 = __half22float2(*(__half2*)&raw.x);
            float2 r1 = __half22float2(*(__half2*)&raw.y);
            v.x += r0.x; v.y += r0.y; v.z += r1.x; v.w += r1.y;
            *(float4*)&out[grow * (size_t)NDIM + gcol] = v;
        }
    }
}

// ---------------- attention: wmma, one block per (window, head-pair) ----------------
// P tiles recycle the qs/ks buffers (dead after the S stage) -> 62.5 KB smem -> 3 CTAs/SM.
#define AQLD 72
#define ASLD 68
#define ATTN_DYN (3 * 64 * AQLD * 2 + 2 * 64 * ASLD * 4)  // 62464 B

__global__ __launch_bounds__(256) void attn_kernel(const __half* __restrict__ qkv,
                                                   __half* __restrict__ o)
{
    extern __shared__ char smraw[];
    __half* qs  = (__half*)smraw;
    __half* ks  = qs + 64 * AQLD;
    __half* vs  = ks + 64 * AQLD;
    float*  ss0 = (float*)(vs + 64 * AQLD);
    float*  ss1 = ss0 + 64 * ASLD;
    __half* ps0 = qs;   // P recycles q tile (dead after S stage barrier)
    __half* ps1 = ks;   // P recycles k tile

    const int hp  = blockIdx.x;
    const int win = blockIdx.y;
    const int tid = threadIdx.x;
    const int wid = tid >> 5;

    const __half* base = qkv + (size_t)win * 36864 + hp * 64;
#pragma unroll
    for (int s = 0; s < 2; s++) {
        int idx = tid + s * 256;
        int r = idx >> 3, c8 = idx & 7;
        const __half* rp = base + (size_t)r * 576 + c8 * 8;
        *(uint4*)&qs[r * AQLD + c8 * 8] = *(const uint4*)(rp);
        *(uint4*)&ks[r * AQLD + c8 * 8] = *(const uint4*)(rp + 192);
        *(uint4*)&vs[r * AQLD + c8 * 8] = *(const uint4*)(rp + 384);
    }
    __syncthreads();

    const int hh    = wid >> 2;
    const int strip = wid & 3;
    float*  ssh = hh ? ss1 : ss0;
    __half* psh = hh ? ps1 : ps0;

    // S = Q K^T
    {
        wmma::fragment<wmma::accumulator, 16, 16, 16, float> acc[4];
#pragma unroll
        for (int t = 0; t < 4; t++) wmma::fill_fragment(acc[t], 0.f);
#pragma unroll
        for (int k0 = 0; k0 < 32; k0 += 16) {
            wmma::fragment<wmma::matrix_a, 16, 16, 16, __half, wmma::row_major> af;
            wmma::load_matrix_sync(af, &qs[strip * 16 * AQLD + hh * 32 + k0], AQLD);
#pragma unroll
            for (int tn = 0; tn < 4; tn++) {
                wmma::fragment<wmma::matrix_b, 16, 16, 16, __half, wmma::col_major> bf;
                wmma::load_matrix_sync(bf, &ks[tn * 16 * AQLD + hh * 32 + k0], AQLD);
                wmma::mma_sync(acc[tn], af, bf, acc[tn]);
            }
        }
#pragma unroll
        for (int tn = 0; tn < 4; tn++)
            wmma::store_matrix_sync(&ssh[strip * 16 * ASLD + tn * 16], acc[tn], ASLD,
                                    wmma::mem_row_major);
    }
    __syncthreads();   // retires all qs/ks reads; P may now overwrite them

    // softmax: thread pair per row; P written into recycled qs/ks
    {
        const int head = tid >> 7;
        const int i    = (tid >> 1) & 63;
        const int half = tid & 1;
        const int j0   = half * 32;
        float* srow = (head ? ss1 : ss0) + i * ASLD + j0;
        float sv[32];
        float m = -1e30f;
#pragma unroll
        for (int jj = 0; jj < 32; jj++) {
            sv[jj] = srow[jj] * 0.17677669529663687f;
            m = fmaxf(m, sv[jj]);
        }
        m = fmaxf(m, __shfl_xor_sync(0xffffffffu, m, 1));
        float sum = 0.f;
#pragma unroll
        for (int jj = 0; jj < 32; jj++) { sv[jj] = __expf(sv[jj] - m); sum += sv[jj]; }
        sum += __shfl_xor_sync(0xffffffffu, sum, 1);
        float rinv = 1.f / sum;
        __half* prow = (head ? ps1 : ps0) + i * AQLD + j0;
#pragma unroll
        for (int jj = 0; jj < 16; jj++) {
            __half2 h = __floats2half2_rn(sv[jj * 2] * rinv, sv[jj * 2 + 1] * rinv);
            *(__half2*)&prow[jj * 2] = h;
        }
    }
    __syncthreads();

    // O = P V   (O staged into S buffers — S is dead after softmax)
    {
        wmma::fragment<wmma::accumulator, 16, 16, 16, float> acc[2];
#pragma unroll
        for (int t = 0; t < 2; t++) wmma::fill_fragment(acc[t], 0.f);
#pragma unroll
        for (int k0 = 0; k0 < 64; k0 += 16) {
            wmma::fragment<wmma::matrix_a, 16, 16, 16, __half, wmma::row_major> af;
            wmma::load_matrix_sync(af, &psh[strip * 16 * AQLD + k0], AQLD);
#pragma unroll
            for (int tn = 0; tn < 2; tn++) {
                wmma::fragment<wmma::matrix_b, 16, 16, 16, __half, wmma::row_major> bf;
                wmma::load_matrix_sync(bf, &vs[k0 * AQLD + hh * 32 + tn * 16], AQLD);
                wmma::mma_sync(acc[tn], af, bf, acc[tn]);
            }
        }
#pragma unroll
        for (int tn = 0; tn < 2; tn++)
            wmma::store_matrix_sync(&ssh[strip * 16 * 36 + tn * 16], acc[tn], 36,
                                    wmma::mem_row_major);
    }
    __syncthreads();

    // write O
    {
        const int head = tid >> 7;
        const int r    = tid & 63;
        const int hf   = (tid >> 6) & 1;
        const int c0   = hf * 16;
        float* srow = (head ? ss1 : ss0) + r * 36 + c0;
        __half* orow = o + (size_t)(win * 64 + r) * 192 + hp * 64 + head * 32 + c0;
        uint4 pack[2];
#pragma unroll
        for (int q = 0; q < 2; q++) {
            float4 a = *(float4*)&srow[q * 8];
            float4 b = *(float4*)&srow[q * 8 + 4];
            __half2 h0 = __floats2half2_rn(a.x, a.y);
            __half2 h1 = __floats2half2_rn(a.z, a.w);
            __half2 h2 = __floats2half2_rn(b.x, b.y);
            __half2 h3 = __floats2half2_rn(b.z, b.w);
            pack[q] = make_uint4(*(uint32_t*)&h0, *(uint32_t*)&h1,
                                 *(uint32_t*)&h2, *(uint32_t*)&h3);
        }
        *(uint4*)&orow[0] = pack[0];
        *(uint4*)&orow[8] = pack[1];
    }
}

// ---------------- launch ----------------
extern "C" void kernel_launch(void* const* d_in, const int* in_sizes, int n_in,
                              void* d_out, int out_size)
{
    (void)in_sizes; (void)n_in; (void)out_size;
    const float* x      = (const float*)d_in[0];
    const float* g1     = (const float*)d_in[1];
    const float* b1     = (const float*)d_in[2];
    const float* w_qkv  = (const float*)d_in[3];
    const float* b_qkv  = (const float*)d_in[4];
    const float* w_proj = (const float*)d_in[5];
    const float* b_proj = (const float*)d_in[6];
    const float* g2     = (const float*)d_in[7];
    const float* b2     = (const float*)d_in[8];
    const float* w_fc1  = (const float*)d_in[9];
    const float* b_fc1  = (const float*)d_in[10];
    const float* w_fc2  = (const float*)d_in[11];
    const float* b_fc2  = (const float*)d_in[12];
    float* out = (float*)d_out;

    __half *ln, *big, *ow, *xo, *wqkv_h, *wproj_h, *wfc1_h, *wfc2_h;
    cudaGetSymbolAddress((void**)&ln,  g_ln);
    cudaGetSymbolAddress((void**)&big, g_big);
    cudaGetSymbolAddress((void**)&ow,  g_ow);
    cudaGetSymbolAddress((void**)&xo,  g_xo);
    cudaGetSymbolAddress((void**)&wqkv_h, g_wqkv_h);
    cudaGetSymbolAddress((void**)&wproj_h, g_wproj_h);
    cudaGetSymbolAddress((void**)&wfc1_h, g_wfc1_h);
    cudaGetSymbolAddress((void**)&wfc2_h, g_wfc2_h);

    const int SB = (int)GEMM_DYN;
    cudaFuncSetAttribute(gemm_kernel<192, 576, EPI_QKV>,  cudaFuncAttributeMaxDynamicSharedMemorySize, SB);
    cudaFuncSetAttribute(gemm_kernel<192, 192, EPI_PROJ>, cudaFuncAttributeMaxDynamicSharedMemorySize, SB);
    cudaFuncSetAttribute(gemm_kernel<192, 768, EPI_FC1>,  cudaFuncAttributeMaxDynamicSharedMemorySize, SB);
    cudaFuncSetAttribute(gemm_kernel<768, 192, EPI_FC2>,  cudaFuncAttributeMaxDynamicSharedMemorySize, SB);
    cudaFuncSetAttribute(attn_kernel, cudaFuncAttributeMaxDynamicSharedMemorySize, ATTN_DYN);

    // 0. all weights fp32 -> fp16, one launch
    {
        int n0 = 192 * 576 / 4, n1 = 192 * 192 / 4, n2 = 192 * 768 / 4, n3 = 768 * 192 / 4;
        int total = n0 + n1 + n2 + n3;
        f2h_all_kernel<<<(total + 255) / 256, 256>>>(w_qkv, wqkv_h, n0, w_proj, wproj_h, n1,
                                                     w_fc1, wfc1_h, n2, w_fc2, wfc2_h, n3);
    }

    // 1. LN1 + window partition (fp32 in, fp16 out)
    ln_kernel<true, float><<<TOK / 8, 256>>>(x, g1, b1, ln);
    // 2. QKV GEMM: 6 column blocks of 96 (fp16 out)
    gemm_kernel<192, 576, EPI_QKV><<<dim3(6, TOK / GBM), NTHRG, SB>>>(ln, wqkv_h, b_qkv, nullptr, big);
    // 3. attention per (window, head-pair), 3 CTAs/SM
    attn_kernel<<<dim3(3, 4096), 256, ATTN_DYN>>>(big, ow);
    // 4. proj GEMM + window unpartition + residual x -> xo (fp16)
    gemm_kernel<192, 192, EPI_PROJ><<<dim3(2, TOK / GBM), NTHRG, SB>>>(ow, wproj_h, b_proj, x, xo);
    // 5. LN2 (fp16 in, fp16 out)
    ln_kernel<false, __half><<<TOK / 8, 256>>>(xo, g2, b2, ln);
    // 6. FC1 GEMM + exact GELU (fp16 out)
    gemm_kernel<192, 768, EPI_FC1><<<dim3(8, TOK / GBM), NTHRG, SB>>>(ln, wfc1_h, b_fc1, nullptr, big);
    // 7. FC2 GEMM + residual xo (fp16) -> out (fp32)
    gemm_kernel<768, 192, EPI_FC2><<<dim3(2, TOK / GBM), NTHRG, SB>>>(big, wfc2_h, b_fc2, xo, out);
}

// round 13
// speedup vs baseline: 1.1737x; 1.1737x over previous
#include <cuda_runtime.h>
#include <cuda_fp16.h>
#include <mma.h>
#include <cstdint>

using namespace nvcuda;

#define TOK    262144          // 4*256*256 tokens
#define CDIM   192

// ---------------- scratch (device globals; no allocation) ----------------
__device__ __half g_ln  [(size_t)TOK * 192];   // LN1 (window layout) then LN2 (token layout)
__device__ __half g_big [(size_t)TOK * 768];   // qkv (576 wide) then fc1 activation (768 wide)
__device__ __half g_ow  [(size_t)TOK * 192];   // attention output, window layout
__device__ __half g_xo  [(size_t)TOK * 192];   // post-attention residual, token layout (fp16)
__device__ __half g_wqkv_h[192 * 576];
__device__ __half g_wproj_h[192 * 192];
__device__ __half g_wfc1_h[192 * 768];
__device__ __half g_wfc2_h[768 * 192];

// ---------------- cp.async helpers ----------------
__device__ __forceinline__ void cp_async16(void* smem_dst, const void* gmem_src) {
    uint32_t s = (uint32_t)__cvta_generic_to_shared(smem_dst);
    asm volatile("cp.async.cg.shared.global [%0], [%1], 16;\n" :: "r"(s), "l"(gmem_src));
}
__device__ __forceinline__ void cp_commit() {
    asm volatile("cp.async.commit_group;\n" ::: "memory");
}
template<int N>
__device__ __forceinline__ void cp_wait() {
    asm volatile("cp.async.wait_group %0;\n" :: "n"(N) : "memory");
}

// ---------------- mma.sync m16n8k16 fp16 -> fp32 ----------------
__device__ __forceinline__ void mma16816(float* c, const uint32_t* a, const uint32_t* b) {
    asm volatile("mma.sync.aligned.m16n8k16.row.col.f32.f16.f16.f32 "
                 "{%0,%1,%2,%3}, {%4,%5,%6,%7}, {%8,%9}, {%0,%1,%2,%3};"
                 : "+f"(c[0]), "+f"(c[1]), "+f"(c[2]), "+f"(c[3])
                 : "r"(a[0]), "r"(a[1]), "r"(a[2]), "r"(a[3]), "r"(b[0]), "r"(b[1]));
}
__device__ __forceinline__ uint32_t packh2(float lo, float hi) {
    __half2 h = __floats2half2_rn(lo, hi);
    return *(uint32_t*)&h;
}

// ---------------- fused fp32 -> fp16 conversion of all four weights ----------------
__global__ __launch_bounds__(256) void f2h_all_kernel(const float* __restrict__ w0, __half* o0, int n0,
                                                      const float* __restrict__ w1, __half* o1, int n1,
                                                      const float* __restrict__ w2, __half* o2, int n2,
                                                      const float* __restrict__ w3, __half* o3, int n3)
{
    int i = blockIdx.x * 256 + threadIdx.x;
    const float* src; __half* dst;
    if (i < n0)                    { src = w0; dst = o0; }
    else if ((i -= n0) < n1)       { src = w1; dst = o1; }
    else if ((i -= n1) < n2)       { src = w2; dst = o2; }
    else if ((i -= n2) < n3)       { src = w3; dst = o3; }
    else return;
    float4 v = *(const float4*)(src + (size_t)i * 4);
    *(uint2*)(dst + (size_t)i * 4) = make_uint2(packh2(v.x, v.y), packh2(v.z, v.w));
}

// ---------------- LayerNorm (one warp per token), templated input, fp16 output ----------------
template<bool WINDOW_DST, typename T>
__global__ __launch_bounds__(256) void ln_kernel(const T* __restrict__ x,
                                                 const float* __restrict__ g,
                                                 const float* __restrict__ b,
                                                 __half* __restrict__ out)
{
    int tok  = blockIdx.x * (blockDim.x >> 5) + (threadIdx.x >> 5);
    int lane = threadIdx.x & 31;
    const T* row = x + (size_t)tok * CDIM;
    float v[6];
    float s = 0.f, s2 = 0.f;
#pragma unroll
    for (int k = 0; k < 6; k++) {
        v[k] = (float)row[lane + 32 * k];
        s  += v[k];
        s2 += v[k] * v[k];
    }
#pragma unroll
    for (int o = 16; o > 0; o >>= 1) {
        s  += __shfl_xor_sync(0xffffffffu, s,  o);
        s2 += __shfl_xor_sync(0xffffffffu, s2, o);
    }
    float mean = s * (1.f / 192.f);
    float var  = s2 * (1.f / 192.f) - mean * mean;
    float inv  = rsqrtf(var + 1e-5f);

    size_t drow;
    if (WINDOW_DST) {
        int bb  = tok >> 16;
        int rem = tok & 65535;
        int h   = rem >> 8;
        int w   = rem & 255;
        int win = (bb << 10) + ((h >> 3) << 5) + (w >> 3);
        int n   = ((h & 7) << 3) + (w & 7);
        drow = (size_t)win * 64 + n;
    } else {
        drow = (size_t)tok;
    }
    __half* orow = out + drow * CDIM;
#pragma unroll
    for (int k = 0; k < 6; k++) {
        int c = lane + 32 * k;
        orow[c] = __float2half_rn((v[k] - mean) * inv * g[c] + b[c]);
    }
}

// ---------------- GEMM: fp16 wmma, 128x96 tile, 256 thr, 3-stage, 2 CTAs/SM (R11) ----------------
#define GBM 128
#define GBN 96
#define GBK 64
#define NTHR 256

#define ALDH 72                   // 64 + 8 halves pad
#define BLDH 104                  // 96 + 8 halves pad
#define SA_HALF (GBM * ALDH)      // 9216 halves
#define SB_HALF (GBK * BLDH)      // 6656 halves
#define STAGE_HALF (SA_HALF + SB_HALF)
#define GEMM_DYN (3 * STAGE_HALF * 2)   // 95232 B; epilogue csm 128*100*4 = 51200 fits
#define CLD 100

enum { EPI_QKV = 0, EPI_PROJ = 1, EPI_FC1 = 2, EPI_FC2 = 3 };

// A: [M][KDIM] half row-major; B: [KDIM][NDIM] half row-major.
// EPI_PROJ: res = x (fp32), out = xo (fp16, token scatter).
// EPI_FC2:  res = xo (fp16), out = final (fp32).
template<int KDIM, int NDIM, int EPI>
__global__ __launch_bounds__(NTHR, 2) void gemm_kernel(const __half* __restrict__ A,
                                                       const __half* __restrict__ B,
                                                       const float* __restrict__ bias,
                                                       const void* __restrict__ res_v,
                                                       void* __restrict__ out_v)
{
    extern __shared__ char dynsm[];
    __half* sbase = (__half*)dynsm;
    float*  csm   = (float*)dynsm;

    const int bn   = blockIdx.x;
    const int bm   = blockIdx.y;
    const int tid  = threadIdx.x;
    const int warp = tid >> 5;
    const int wr   = warp >> 1;   // 0..3 : 32-row group
    const int wc   = warp & 1;    // 0..1 : 48-col group

    const __half* Abase = A + (size_t)(bm * GBM) * KDIM;
    const __half* Bbase = B + (size_t)bn * GBN;

    wmma::fragment<wmma::accumulator, 16, 16, 16, float> acc[2][3];
#pragma unroll
    for (int i = 0; i < 2; i++)
#pragma unroll
        for (int j = 0; j < 3; j++) wmma::fill_fragment(acc[i][j], 0.f);

    auto issue_stage = [&](int st, int k0) {
        __half* sa = sbase + st * STAGE_HALF;
        __half* sb = sa + SA_HALF;
#pragma unroll
        for (int s = 0; s < 4; s++) {
            int line = tid + s * NTHR;
            int r = line >> 3, c8 = line & 7;
            cp_async16(&sa[r * ALDH + c8 * 8],
                       Abase + (size_t)r * KDIM + k0 + c8 * 8);
        }
#pragma unroll
        for (int s = 0; s < 3; s++) {
            int line = tid + s * NTHR;
            int r = line / 12, c8 = line % 12;
            cp_async16(&sb[r * BLDH + c8 * 8],
                       Bbase + (size_t)(k0 + r) * NDIM + c8 * 8);
        }
        cp_commit();
    };

    constexpr int NK = KDIM / GBK;
    issue_stage(0, 0);
    if (NK > 1) issue_stage(1, GBK);

    // Single-barrier mainloop: wait(cur) -> barrier -> issue(kt+2) -> compute(kt).
#pragma unroll 1
    for (int kt = 0; kt < NK; kt++) {
        if (kt + 1 < NK) cp_wait<1>(); else cp_wait<0>();
        __syncthreads();
        if (kt + 2 < NK) issue_stage((kt + 2) % 3, (kt + 2) * GBK);

        const __half* sa = sbase + (kt % 3) * STAGE_HALF;
        const __half* sb = sa + SA_HALF;
#pragma unroll
        for (int kk = 0; kk < GBK; kk += 16) {
            wmma::fragment<wmma::matrix_a, 16, 16, 16, __half, wmma::row_major> af[2];
            wmma::fragment<wmma::matrix_b, 16, 16, 16, __half, wmma::row_major> bf[3];
#pragma unroll
            for (int i = 0; i < 2; i++)
                wmma::load_matrix_sync(af[i], &sa[(wr * 32 + i * 16) * ALDH + kk], ALDH);
#pragma unroll
            for (int j = 0; j < 3; j++)
                wmma::load_matrix_sync(bf[j], &sb[kk * BLDH + wc * 48 + j * 16], BLDH);
#pragma unroll
            for (int i = 0; i < 2; i++)
#pragma unroll
                for (int j = 0; j < 3; j++)
                    wmma::mma_sync(acc[i][j], af[i], bf[j], acc[i][j]);
        }
    }
    __syncthreads();   // all compute done before csm overwrites stage buffers

#pragma unroll
    for (int i = 0; i < 2; i++)
#pragma unroll
        for (int j = 0; j < 3; j++)
            wmma::store_matrix_sync(&csm[(wr * 32 + i * 16) * CLD + wc * 48 + j * 16],
                                    acc[i][j], CLD, wmma::mem_row_major);
    __syncthreads();

    // epilogue: 128x96 = 3072 float4-groups, 12 per thread
#pragma unroll
    for (int e = tid; e < GBM * (GBN / 4); e += NTHR) {
        int r  = e / 24;
        int c4 = e % 24;
        int gcol = bn * GBN + c4 * 4;
        size_t grow = (size_t)bm * GBM + r;
        float4 v  = *(float4*)&csm[r * CLD + c4 * 4];
        float4 bb = *(const float4*)&bias[gcol];
        v.x += bb.x; v.y += bb.y; v.z += bb.z; v.w += bb.w;

        if constexpr (EPI == EPI_QKV) {
            __half* out = (__half*)out_v;
            *(uint2*)&out[grow * NDIM + gcol] = make_uint2(packh2(v.x, v.y), packh2(v.z, v.w));
        } else if constexpr (EPI == EPI_PROJ) {
            __half* out = (__half*)out_v;              // xo fp16
            const float* res = (const float*)res_v;    // original x fp32
            int rg  = (int)grow;
            int win = rg >> 6, n = rg & 63;
            int bbi = win >> 10, wrw = win & 1023;
            int h   = ((wrw >> 5) << 3) + (n >> 3);
            int w   = ((wrw & 31) << 3) + (n & 7);
            size_t t = ((size_t)bbi << 16) + ((size_t)h << 8) + (size_t)w;
            float4 rr = *(const float4*)&res[t * CDIM + gcol];
            v.x += rr.x; v.y += rr.y; v.z += rr.z; v.w += rr.w;
            *(uint2*)&out[t * CDIM + gcol] = make_uint2(packh2(v.x, v.y), packh2(v.z, v.w));
        } else if constexpr (EPI == EPI_FC1) {
            __half* out = (__half*)out_v;
            v.x *= normcdff(v.x); v.y *= normcdff(v.y);
            v.z *= normcdff(v.z); v.w *= normcdff(v.w);
            *(uint2*)&out[grow * NDIM + gcol] = make_uint2(packh2(v.x, v.y), packh2(v.z, v.w));
        } else {  // EPI_FC2
            float* out = (float*)out_v;
            const __half* res = (const __half*)res_v;  // xo fp16
            uint2 raw = *(const uint2*)&res[grow * (size_t)CDIM + gcol];
            float2 r0 = __half22float2(*(__half2*)&raw.x);
            float2 r1 = __half22float2(*(__half2*)&raw.y);
            v.x += r0.x; v.y += r0.y; v.z += r1.x; v.w += r1.y;
            *(float4*)&out[grow * (size_t)NDIM + gcol] = v;
        }
    }
}

// ---------------- attention: register-softmax mma.sync pipeline ----------------
// Block = (head-pair hp, window). 8 warps: hh = wid>>2 (head), strip = wid&3 (16 rows).
// S and P live entirely in registers; one barrier total. smem = q/k/v tiles only.
#define AQLD 72
#define ATTN_DYN (3 * 64 * AQLD * 2)   // 27648 B

__global__ __launch_bounds__(256) void attn_kernel(const __half* __restrict__ qkv,
                                                   __half* __restrict__ o)
{
    extern __shared__ char smraw[];
    __half* qs = (__half*)smraw;
    __half* ks = qs + 64 * AQLD;
    __half* vs = ks + 64 * AQLD;

    const int hp  = blockIdx.x;
    const int win = blockIdx.y;
    const int tid = threadIdx.x;
    const int wid = tid >> 5;
    const int lane = tid & 31;

    const __half* base = qkv + (size_t)win * 36864 + hp * 64;
#pragma unroll
    for (int s = 0; s < 2; s++) {
        int idx = tid + s * 256;
        int r = idx >> 3, c8 = idx & 7;
        const __half* rp = base + (size_t)r * 576 + c8 * 8;
        *(uint4*)&qs[r * AQLD + c8 * 8] = *(const uint4*)(rp);
        *(uint4*)&ks[r * AQLD + c8 * 8] = *(const uint4*)(rp + 192);
        *(uint4*)&vs[r * AQLD + c8 * 8] = *(const uint4*)(rp + 384);
    }
    __syncthreads();

    const int hh    = wid >> 2;     // head within pair
    const int strip = wid & 3;      // 16-row strip
    const int gid   = lane >> 2;    // 0..7  (row within 8-group / B column)
    const int tig   = lane & 3;     // 0..3  (k-pair index)
    const int r1    = strip * 16 + gid;   // rows r1, r1+8
    const int kb    = hh * 32;

    // Q A-fragments: 2 k-tiles of 16
    uint32_t aq[2][4];
#pragma unroll
    for (int kt = 0; kt < 2; kt++) {
        int k0 = kb + kt * 16 + tig * 2;
        aq[kt][0] = *(uint32_t*)&qs[r1 * AQLD + k0];
        aq[kt][1] = *(uint32_t*)&qs[(r1 + 8) * AQLD + k0];
        aq[kt][2] = *(uint32_t*)&qs[r1 * AQLD + k0 + 8];
        aq[kt][3] = *(uint32_t*)&qs[(r1 + 8) * AQLD + k0 + 8];
    }

    // S = Q K^T : 8 j-tiles (m16n8), accumulate over 2 k-tiles
    float sc[8][4];
#pragma unroll
    for (int jt = 0; jt < 8; jt++) { sc[jt][0] = sc[jt][1] = sc[jt][2] = sc[jt][3] = 0.f; }
#pragma unroll
    for (int jt = 0; jt < 8; jt++) {
        int jr = jt * 8 + gid;
#pragma unroll
        for (int kt = 0; kt < 2; kt++) {
            int k0 = kb + kt * 16 + tig * 2;
            uint32_t bf[2];
            bf[0] = *(uint32_t*)&ks[jr * AQLD + k0];
            bf[1] = *(uint32_t*)&ks[jr * AQLD + k0 + 8];
            mma16816(sc[jt], aq[kt], bf);
        }
    }

    // register softmax over rows r1 (c0,c1) and r1+8 (c2,c3); reduce across lane quad
    const float scale = 0.17677669529663687f;
    float m1 = -1e30f, m2 = -1e30f;
#pragma unroll
    for (int jt = 0; jt < 8; jt++) {
        sc[jt][0] *= scale; sc[jt][1] *= scale; sc[jt][2] *= scale; sc[jt][3] *= scale;
        m1 = fmaxf(m1, fmaxf(sc[jt][0], sc[jt][1]));
        m2 = fmaxf(m2, fmaxf(sc[jt][2], sc[jt][3]));
    }
    m1 = fmaxf(m1, __shfl_xor_sync(0xffffffffu, m1, 1));
    m1 = fmaxf(m1, __shfl_xor_sync(0xffffffffu, m1, 2));
    m2 = fmaxf(m2, __shfl_xor_sync(0xffffffffu, m2, 1));
    m2 = fmaxf(m2, __shfl_xor_sync(0xffffffffu, m2, 2));
    float s1 = 0.f, s2 = 0.f;
#pragma unroll
    for (int jt = 0; jt < 8; jt++) {
        sc[jt][0] = __expf(sc[jt][0] - m1); sc[jt][1] = __expf(sc[jt][1] - m1);
        sc[jt][2] = __expf(sc[jt][2] - m2); sc[jt][3] = __expf(sc[jt][3] - m2);
        s1 += sc[jt][0] + sc[jt][1];
        s2 += sc[jt][2] + sc[jt][3];
    }
    s1 += __shfl_xor_sync(0xffffffffu, s1, 1);
    s1 += __shfl_xor_sync(0xffffffffu, s1, 2);
    s2 += __shfl_xor_sync(0xffffffffu, s2, 1);
    s2 += __shfl_xor_sync(0xffffffffu, s2, 2);
    float i1 = 1.f / s1, i2 = 1.f / s2;

    // P -> fp16 A-fragment halves (row, col-pair mapping matches A frag exactly)
    uint32_t phr1[8], phr2[8];
#pragma unroll
    for (int jt = 0; jt < 8; jt++) {
        phr1[jt] = packh2(sc[jt][0] * i1, sc[jt][1] * i1);
        phr2[jt] = packh2(sc[jt][2] * i2, sc[jt][3] * i2);
    }

    // O = P V : 4 k-tiles (j), 4 n-tiles (8 d each)
    float oc[4][4];
#pragma unroll
    for (int nt = 0; nt < 4; nt++) { oc[nt][0] = oc[nt][1] = oc[nt][2] = oc[nt][3] = 0.f; }
#pragma unroll
    for (int kt = 0; kt < 4; kt++) {
        uint32_t pa[4] = { phr1[2 * kt], phr2[2 * kt], phr1[2 * kt + 1], phr2[2 * kt + 1] };
        int k0 = kt * 16 + tig * 2;
#pragma unroll
        for (int nt = 0; nt < 4; nt++) {
            int d = kb + nt * 8 + gid;
            uint32_t bf[2];
            bf[0] = packh2(0.f, 0.f);   // overwritten below
            __half b00 = vs[(size_t)k0 * AQLD + d];
            __half b01 = vs[(size_t)(k0 + 1) * AQLD + d];
            __half b10 = vs[(size_t)(k0 + 8) * AQLD + d];
            __half b11 = vs[(size_t)(k0 + 9) * AQLD + d];
            __half2 h0 = __halves2half2(b00, b01);
            __half2 h1 = __halves2half2(b10, b11);
            bf[0] = *(uint32_t*)&h0;
            bf[1] = *(uint32_t*)&h1;
            mma16816(oc[nt], pa, bf);
        }
    }

    // write O straight from accumulators (rows r1, r1+8; cols tig*2,+1 per n-tile)
    size_t ro1 = (size_t)(win * 64 + r1) * 192 + hp * 64 + kb;
    size_t ro2 = ro1 + (size_t)8 * 192;
#pragma unroll
    for (int nt = 0; nt < 4; nt++) {
        int dc = nt * 8 + tig * 2;
        *(uint32_t*)&o[ro1 + dc] = packh2(oc[nt][0], oc[nt][1]);
        *(uint32_t*)&o[ro2 + dc] = packh2(oc[nt][2], oc[nt][3]);
    }
}

// ---------------- launch ----------------
extern "C" void kernel_launch(void* const* d_in, const int* in_sizes, int n_in,
                              void* d_out, int out_size)
{
    (void)in_sizes; (void)n_in; (void)out_size;
    const float* x      = (const float*)d_in[0];
    const float* g1     = (const float*)d_in[1];
    const float* b1     = (const float*)d_in[2];
    const float* w_qkv  = (const float*)d_in[3];
    const float* b_qkv  = (const float*)d_in[4];
    const float* w_proj = (const float*)d_in[5];
    const float* b_proj = (const float*)d_in[6];
    const float* g2     = (const float*)d_in[7];
    const float* b2     = (const float*)d_in[8];
    const float* w_fc1  = (const float*)d_in[9];
    const float* b_fc1  = (const float*)d_in[10];
    const float* w_fc2  = (const float*)d_in[11];
    const float* b_fc2  = (const float*)d_in[12];
    float* out = (float*)d_out;

    __half *ln, *big, *ow, *xo, *wqkv_h, *wproj_h, *wfc1_h, *wfc2_h;
    cudaGetSymbolAddress((void**)&ln,  g_ln);
    cudaGetSymbolAddress((void**)&big, g_big);
    cudaGetSymbolAddress((void**)&ow,  g_ow);
    cudaGetSymbolAddress((void**)&xo,  g_xo);
    cudaGetSymbolAddress((void**)&wqkv_h, g_wqkv_h);
    cudaGetSymbolAddress((void**)&wproj_h, g_wproj_h);
    cudaGetSymbolAddress((void**)&wfc1_h, g_wfc1_h);
    cudaGetSymbolAddress((void**)&wfc2_h, g_wfc2_h);

    const int SB = (int)GEMM_DYN;
    cudaFuncSetAttribute(gemm_kernel<192, 576, EPI_QKV>,  cudaFuncAttributeMaxDynamicSharedMemorySize, SB);
    cudaFuncSetAttribute(gemm_kernel<192, 192, EPI_PROJ>, cudaFuncAttributeMaxDynamicSharedMemorySize, SB);
    cudaFuncSetAttribute(gemm_kernel<192, 768, EPI_FC1>,  cudaFuncAttributeMaxDynamicSharedMemorySize, SB);
    cudaFuncSetAttribute(gemm_kernel<768, 192, EPI_FC2>,  cudaFuncAttributeMaxDynamicSharedMemorySize, SB);

    // 0. all weights fp32 -> fp16, one launch
    {
        int n0 = 192 * 576 / 4, n1 = 192 * 192 / 4, n2 = 192 * 768 / 4, n3 = 768 * 192 / 4;
        int total = n0 + n1 + n2 + n3;
        f2h_all_kernel<<<(total + 255) / 256, 256>>>(w_qkv, wqkv_h, n0, w_proj, wproj_h, n1,
                                                     w_fc1, wfc1_h, n2, w_fc2, wfc2_h, n3);
    }

    // 1. LN1 + window partition (fp32 in, fp16 out)
    ln_kernel<true, float><<<TOK / 8, 256>>>(x, g1, b1, ln);
    // 2. QKV GEMM: 6 column blocks of 96 (fp16 out)
    gemm_kernel<192, 576, EPI_QKV><<<dim3(6, TOK / GBM), NTHR, SB>>>(ln, wqkv_h, b_qkv, nullptr, big);
    // 3. attention per (head-pair, window): register softmax pipeline
    attn_kernel<<<dim3(3, 4096), 256, ATTN_DYN>>>(big, ow);
    // 4. proj GEMM + window unpartition + residual x -> xo (fp16)
    gemm_kernel<192, 192, EPI_PROJ><<<dim3(2, TOK / GBM), NTHR, SB>>>(ow, wproj_h, b_proj, x, xo);
    // 5. LN2 (fp16 in, fp16 out)
    ln_kernel<false, __half><<<TOK / 8, 256>>>(xo, g2, b2, ln);
    // 6. FC1 GEMM + exact GELU (fp16 out)
    gemm_kernel<192, 768, EPI_FC1><<<dim3(8, TOK / GBM), NTHR, SB>>>(ln, wfc1_h, b_fc1, nullptr, big);
    // 7. FC2 GEMM + residual xo (fp16) -> out (fp32)
    gemm_kernel<768, 192, EPI_FC2><<<dim3(2, TOK / GBM), NTHR, SB>>>(big, wfc2_h, b_fc2, xo, out);
}